// round 1
// baseline (speedup 1.0000x reference)
#include <cuda_runtime.h>

// Problem constants
#define NB   32
#define SS   2048
#define CI   256
#define CO   256
#define KW   16
#define TOUT 2033          // SS - KW + 1

// Tiling
#define MT   128           // output t-rows per block
#define NT   64            // output channels per block
#define CC   4             // input channels per chunk
#define XT   (MT + KW - 1) // 143 x-rows needed per tile
#define XTP  144           // padded

// Precomputed effective weights, layout [i][k][o] (o contiguous)
__device__ float g_weff[CI * KW * CO];

__global__ void weff_kernel(const float* __restrict__ wr,
                            const float* __restrict__ wi,
                            const float* __restrict__ ph) {
    int idx = blockIdx.x * blockDim.x + threadIdx.x;
    if (idx >= CI * KW * CO) return;
    int o = idx & (CO - 1);
    int k = (idx >> 8) & (KW - 1);
    int i = idx >> 12;
    float s, c;
    sincosf(ph[k], &s, &c);
    int widx = (o * CI + i) * KW + k;   // w_real/w_imag are [o][i][k]
    g_weff[idx] = c * wr[widx] - s * wi[widx];
}

// out[b,t,o] = sum_{k,i} x[b,t+k,i] * w_eff[i,k,o]
__global__ __launch_bounds__(256, 2)
void conv_kernel(const float* __restrict__ x, float* __restrict__ out) {
    __shared__ __align__(16) float xs[CC * XTP];          // [ci][t]
    __shared__ __align__(16) float ws[CC * KW * NT];      // [ci][k][o]

    const int tid = threadIdx.x;
    const int tn  = tid & 15;      // 16 n-threads  -> 4 cols each
    const int tm  = tid >> 4;      // 16 m-threads  -> 8 rows each (stride 16)
    const int t0  = blockIdx.x * MT;
    const int o0  = blockIdx.y * NT;
    const int b   = blockIdx.z;

    const float* xb = x + (size_t)b * SS * CI;

    float acc[8][4];
#pragma unroll
    for (int i = 0; i < 8; i++)
#pragma unroll
        for (int j = 0; j < 4; j++) acc[i][j] = 0.f;

    for (int ci0 = 0; ci0 < CI; ci0 += CC) {
        // ---- load x tile: rows t0..t0+142, CC channels as one float4/row ----
        if (tid < XT) {
            int row = t0 + tid;
            float4 v = make_float4(0.f, 0.f, 0.f, 0.f);
            if (row < SS)
                v = *reinterpret_cast<const float4*>(xb + (size_t)row * CI + ci0);
            xs[0 * XTP + tid] = v.x;
            xs[1 * XTP + tid] = v.y;
            xs[2 * XTP + tid] = v.z;
            xs[3 * XTP + tid] = v.w;
        }
        // ---- load w tile: CC*KW*NT = 4096 floats = 1024 float4 ----
#pragma unroll
        for (int r = 0; r < 4; r++) {
            int l4 = r * 256 + tid;      // float4 index 0..1023
            int o4 = l4 & 15;            // 16 float4 per (c,k)
            int pr = l4 >> 4;            // 0..63 = c*KW + k
            int c  = pr >> 4;
            int k  = pr & 15;
            float4 wv = *reinterpret_cast<const float4*>(
                g_weff + ((size_t)(ci0 + c) * KW + k) * CO + o0 + o4 * 4);
            *reinterpret_cast<float4*>(ws + (c * KW + k) * NT + o4 * 4) = wv;
        }
        __syncthreads();

        // ---- compute: for each (ci, k) rank-1 update into 8x4 tile ----
#pragma unroll 2
        for (int c = 0; c < CC; c++) {
#pragma unroll
            for (int k = 0; k < KW; k++) {
                float4 bv = *reinterpret_cast<const float4*>(
                    ws + (c * KW + k) * NT + tn * 4);
#pragma unroll
                for (int mm = 0; mm < 8; mm++) {
                    float a = xs[c * XTP + mm * 16 + tm + k];
                    acc[mm][0] += a * bv.x;
                    acc[mm][1] += a * bv.y;
                    acc[mm][2] += a * bv.z;
                    acc[mm][3] += a * bv.w;
                }
            }
        }
        __syncthreads();
    }

    // ---- store (guard tail t >= TOUT) ----
#pragma unroll
    for (int mm = 0; mm < 8; mm++) {
        int t = t0 + mm * 16 + tm;
        if (t < TOUT) {
            float4 v = make_float4(acc[mm][0], acc[mm][1], acc[mm][2], acc[mm][3]);
            *reinterpret_cast<float4*>(
                out + ((size_t)b * TOUT + t) * CO + o0 + tn * 4) = v;
        }
    }
}

extern "C" void kernel_launch(void* const* d_in, const int* in_sizes, int n_in,
                              void* d_out, int out_size) {
    const float* x  = (const float*)d_in[0];
    const float* wr = (const float*)d_in[1];
    const float* wi = (const float*)d_in[2];
    const float* ph = (const float*)d_in[3];
    float* out = (float*)d_out;

    (void)in_sizes; (void)n_in; (void)out_size;

    int nw = CI * KW * CO;
    weff_kernel<<<(nw + 255) / 256, 256>>>(wr, wi, ph);

    dim3 grid((TOUT + MT - 1) / MT, CO / NT, NB);   // 16 x 4 x 32
    conv_kernel<<<grid, 256>>>(x, out);
}

// round 2
// speedup vs baseline: 1.2179x; 1.2179x over previous
#include <cuda_runtime.h>

// Problem constants
#define NB   32
#define SS   2048
#define CI   256
#define CO   256
#define KW   16
#define TOUT 2033          // SS - KW + 1

// Tiling
#define MT   128           // output t-rows per block
#define NT   64            // output channels per block
#define CC   4             // input channels per chunk
#define XT   (MT + KW - 1) // 143 x-rows needed per tile
#define XTP  144           // padded (float4-aligned per channel row)

// Precomputed effective weights, layout [i][k][o] (o contiguous)
__device__ float g_weff[CI * KW * CO];

__global__ void weff_kernel(const float* __restrict__ wr,
                            const float* __restrict__ wi,
                            const float* __restrict__ ph) {
    int idx = blockIdx.x * blockDim.x + threadIdx.x;
    if (idx >= CI * KW * CO) return;
    int o = idx & (CO - 1);
    int k = (idx >> 8) & (KW - 1);
    int i = idx >> 12;
    float s, c;
    sincosf(ph[k], &s, &c);
    int widx = (o * CI + i) * KW + k;   // w_real/w_imag are [o][i][k]
    g_weff[idx] = c * wr[widx] - s * wi[widx];
}

// out[b,t,o] = sum_{k,i} x[b,t+k,i] * w_eff[i,k,o]
__global__ __launch_bounds__(256, 2)
void conv_kernel(const float* __restrict__ x, float* __restrict__ out) {
    __shared__ __align__(16) float xs[CC * XTP];          // [ci][t]
    __shared__ __align__(16) float ws[CC * KW * NT];      // [ci][k][o]

    const int tid = threadIdx.x;
    const int tn  = tid & 15;      // 16 n-threads  -> 4 cols each
    const int tm  = tid >> 4;      // 16 m-threads  -> 8 CONTIGUOUS rows each
    const int t0  = blockIdx.x * MT;
    const int o0  = blockIdx.y * NT;
    const int b   = blockIdx.z;

    const float* xb = x + (size_t)b * SS * CI;

    float acc[8][4];
#pragma unroll
    for (int i = 0; i < 8; i++)
#pragma unroll
        for (int j = 0; j < 4; j++) acc[i][j] = 0.f;

    for (int ci0 = 0; ci0 < CI; ci0 += CC) {
        // ---- load x tile: rows t0..t0+142, CC channels as one float4/row ----
        if (tid < XT) {
            int row = t0 + tid;
            float4 v = make_float4(0.f, 0.f, 0.f, 0.f);
            if (row < SS)
                v = *reinterpret_cast<const float4*>(xb + (size_t)row * CI + ci0);
            xs[0 * XTP + tid] = v.x;
            xs[1 * XTP + tid] = v.y;
            xs[2 * XTP + tid] = v.z;
            xs[3 * XTP + tid] = v.w;
        }
        // ---- load w tile: CC*KW*NT = 4096 floats = 1024 float4 ----
#pragma unroll
        for (int r = 0; r < 4; r++) {
            int l4 = r * 256 + tid;      // float4 index 0..1023
            int o4 = l4 & 15;            // 16 float4 per (c,k)
            int pr = l4 >> 4;            // 0..63 = c*KW + k
            int c  = pr >> 4;
            int k  = pr & 15;
            float4 wv = *reinterpret_cast<const float4*>(
                g_weff + ((size_t)(ci0 + c) * KW + k) * CO + o0 + o4 * 4);
            *reinterpret_cast<float4*>(ws + (c * KW + k) * NT + o4 * 4) = wv;
        }
        __syncthreads();

        // ---- compute ----
        // Thread owns rows tm*8 .. tm*8+7.  For each ci, it needs x values
        // tm*8 .. tm*8+22 (23 consecutive floats), 32B-aligned start ->
        // load as 6 x LDS.128 into registers, reuse across all 16 k-shifts.
#pragma unroll
        for (int c = 0; c < CC; c++) {
            float xr[24];
            const float4* xp =
                reinterpret_cast<const float4*>(xs + c * XTP) + tm * 2;
#pragma unroll
            for (int q = 0; q < 6; q++) {
                float4 v = xp[q];
                xr[q * 4 + 0] = v.x;
                xr[q * 4 + 1] = v.y;
                xr[q * 4 + 2] = v.z;
                xr[q * 4 + 3] = v.w;
            }
#pragma unroll
            for (int k = 0; k < KW; k++) {
                float4 bv = *reinterpret_cast<const float4*>(
                    ws + (c * KW + k) * NT + tn * 4);
#pragma unroll
                for (int mm = 0; mm < 8; mm++) {
                    float a = xr[mm + k];
                    acc[mm][0] += a * bv.x;
                    acc[mm][1] += a * bv.y;
                    acc[mm][2] += a * bv.z;
                    acc[mm][3] += a * bv.w;
                }
            }
        }
        __syncthreads();
    }

    // ---- store (guard tail t >= TOUT) ----
#pragma unroll
    for (int mm = 0; mm < 8; mm++) {
        int t = t0 + tm * 8 + mm;
        if (t < TOUT) {
            float4 v = make_float4(acc[mm][0], acc[mm][1], acc[mm][2], acc[mm][3]);
            *reinterpret_cast<float4*>(
                out + ((size_t)b * TOUT + t) * CO + o0 + tn * 4) = v;
        }
    }
}

extern "C" void kernel_launch(void* const* d_in, const int* in_sizes, int n_in,
                              void* d_out, int out_size) {
    const float* x  = (const float*)d_in[0];
    const float* wr = (const float*)d_in[1];
    const float* wi = (const float*)d_in[2];
    const float* ph = (const float*)d_in[3];
    float* out = (float*)d_out;

    (void)in_sizes; (void)n_in; (void)out_size;

    int nw = CI * KW * CO;
    weff_kernel<<<(nw + 255) / 256, 256>>>(wr, wi, ph);

    dim3 grid((TOUT + MT - 1) / MT, CO / NT, NB);   // 16 x 4 x 32
    conv_kernel<<<grid, 256>>>(x, out);
}

// round 4
// speedup vs baseline: 2.6206x; 2.1518x over previous
#include <cuda_runtime.h>
#include <cuda_bf16.h>
#include <cstdint>

#define NB   32
#define SS   2048
#define SPAD 2064
#define CI   256
#define CO   256
#define KW   16
#define TOUT 2033

#define MT   128           // t rows per CTA
#define NT   128           // o cols per CTA
#define ICH  32            // i-channels per reduction chunk
#define NIC  (CI / ICH)    // 8
#define AROWS 143          // x rows per chunk (128 + 15)

#define ASTRIDE 80         // bytes/row in smem (32 bf16 = 64B + 16B pad)
#define BSTRIDE 80

#define A_LO_OFF (144 * ASTRIDE)            // 11520
#define A_BYTES  (2 * 144 * ASTRIDE)        // 23040
#define B_OFF    A_BYTES
#define B_LO_OFF (128 * BSTRIDE)            // within a stage
#define B_STAGE  (2 * 128 * BSTRIDE)        // 20480 (hi+lo)
#define SMEM_TOTAL (A_BYTES + 2 * B_STAGE)  // 64000

// ---------------- device scratch ----------------
__device__ __nv_bfloat16 g_xhi[(size_t)NB * SPAD * CI];
__device__ __nv_bfloat16 g_xlo[(size_t)NB * SPAD * CI];
__device__ __nv_bfloat16 g_whi[(size_t)KW * CO * CI];   // [k][o][i]
__device__ __nv_bfloat16 g_wlo[(size_t)KW * CO * CI];

// ---------------- helpers ----------------
__device__ __forceinline__ uint32_t s2u(const void* p) {
    uint32_t a;
    asm("{ .reg .u64 t; cvta.to.shared.u64 t, %1; cvt.u32.u64 %0, t; }"
        : "=r"(a) : "l"(p));
    return a;
}
__device__ __forceinline__ void cp16(uint32_t d, const void* s) {
    asm volatile("cp.async.cg.shared.global [%0], [%1], 16;" :: "r"(d), "l"(s));
}
__device__ __forceinline__ void cp_commit() {
    asm volatile("cp.async.commit_group;" ::: "memory");
}
__device__ __forceinline__ void cp_wait1() {
    asm volatile("cp.async.wait_group 1;" ::: "memory");
}
__device__ __forceinline__ void cp_wait0() {
    asm volatile("cp.async.wait_group 0;" ::: "memory");
}
__device__ __forceinline__ uint32_t lds32(uint32_t a) {
    uint32_t v;
    asm volatile("ld.shared.b32 %0, [%1];" : "=r"(v) : "r"(a));
    return v;
}
__device__ __forceinline__ void mma16816(float* c, const uint32_t* a, const uint32_t* b) {
    asm volatile(
        "mma.sync.aligned.m16n8k16.row.col.f32.bf16.bf16.f32 "
        "{%0,%1,%2,%3}, {%4,%5,%6,%7}, {%8,%9}, {%0,%1,%2,%3};"
        : "+f"(c[0]), "+f"(c[1]), "+f"(c[2]), "+f"(c[3])
        : "r"(a[0]), "r"(a[1]), "r"(a[2]), "r"(a[3]), "r"(b[0]), "r"(b[1]));
}

// ---------------- prep kernels ----------------
__global__ void xprep_kernel(const float* __restrict__ x) {
    size_t idx = (size_t)blockIdx.x * 256 + threadIdx.x;
    if (idx >= (size_t)NB * SPAD * CI) return;
    int i = idx & (CI - 1);
    size_t r = idx >> 8;
    int t = (int)(r % SPAD);
    int b = (int)(r / SPAD);
    float v = 0.f;
    if (t < SS) v = x[((size_t)b * SS + t) * CI + i];
    __nv_bfloat16 h = __float2bfloat16(v);
    g_xhi[idx] = h;
    g_xlo[idx] = __float2bfloat16(v - __bfloat162float(h));
}

__global__ void wprep_kernel(const float* __restrict__ wr,
                             const float* __restrict__ wi,
                             const float* __restrict__ ph) {
    int idx = blockIdx.x * 256 + threadIdx.x;
    if (idx >= KW * CO * CI) return;
    int i = idx & (CI - 1);
    int o = (idx >> 8) & (CO - 1);
    int k = idx >> 16;
    float s, c;
    sincosf(ph[k], &s, &c);
    int widx = (o * CI + i) * KW + k;            // w_real/w_imag are [o][i][k]
    float v = c * wr[widx] - s * wi[widx];
    __nv_bfloat16 h = __float2bfloat16(v);
    g_whi[idx] = h;
    g_wlo[idx] = __float2bfloat16(v - __bfloat162float(h));
}

// ---------------- main HMMA kernel ----------------
__global__ __launch_bounds__(256, 1)
void conv_mma_kernel(float* __restrict__ out) {
    extern __shared__ char smem[];
    const uint32_t sb = s2u(smem);
    const int tid = threadIdx.x;
    const int l = tid & 31, wid = tid >> 5;
    const int wm = wid & 3, wn = wid >> 2;      // warp grid 4(m) x 2(n)
    const int t0 = blockIdx.x * MT;
    const int b  = blockIdx.y;
    const int o0 = blockIdx.z * NT;

    const char* gxhi = (const char*)g_xhi;
    const char* gxlo = (const char*)g_xlo;
    const char* gwhi = (const char*)g_whi;
    const char* gwlo = (const char*)g_wlo;

    float acc[2][8][4];
#pragma unroll
    for (int mt = 0; mt < 2; mt++)
#pragma unroll
        for (int n = 0; n < 8; n++)
#pragma unroll
            for (int q = 0; q < 4; q++) acc[mt][n][q] = 0.f;

    const int lr = l >> 2;        // 0..7 (row within 8-row group)
    const int lc = l & 3;         // 0..3 (col pair)

    for (int ic = 0; ic < NIC; ic++) {
        const size_t ioff = (size_t)ic * ICH * 2;   // byte offset into i dim

        // ---- A chunk (143 rows x 32 i, hi+lo), single-buffered ----
        for (int u = tid; u < AROWS * 4; u += 256) {
            int row = u >> 2, seg = u & 3;
            size_t g = ((size_t)(b * SPAD + t0 + row)) * (CI * 2) + ioff + seg * 16;
            uint32_t so = row * ASTRIDE + seg * 16;
            cp16(sb + so, gxhi + g);
            cp16(sb + A_LO_OFF + so, gxlo + g);
        }
        // ---- B[k=0] -> stage 0 ----
        {
            uint32_t bs = sb + B_OFF;
#pragma unroll
            for (int q = 0; q < 2; q++) {
                int u = q * 256 + tid;
                int o = u >> 2, seg = u & 3;
                size_t g = ((size_t)(o0 + o)) * (CI * 2) + ioff + seg * 16;
                cp16(bs + o * BSTRIDE + seg * 16, gwhi + g);
                cp16(bs + B_LO_OFF + o * BSTRIDE + seg * 16, gwlo + g);
            }
        }
        cp_commit();

        for (int k = 0; k < KW; k++) {
            const int s = k & 1;
            if (k + 1 < KW) {
                uint32_t bs = sb + B_OFF + (s ^ 1) * B_STAGE;
#pragma unroll
                for (int q = 0; q < 2; q++) {
                    int u = q * 256 + tid;
                    int o = u >> 2, seg = u & 3;
                    size_t g = ((size_t)((k + 1) * CO + o0 + o)) * (CI * 2) + ioff + seg * 16;
                    cp16(bs + o * BSTRIDE + seg * 16, gwhi + g);
                    cp16(bs + B_LO_OFF + o * BSTRIDE + seg * 16, gwlo + g);
                }
                cp_commit();
                cp_wait1();
            } else {
                cp_wait0();
            }
            __syncthreads();

            const uint32_t arow0 = sb + (uint32_t)(k + wm * 32 + lr) * ASTRIDE + lc * 4;
            const uint32_t bbase = sb + B_OFF + s * B_STAGE
                                 + (uint32_t)(wn * 64 + lr) * BSTRIDE + lc * 4;
#pragma unroll
            for (int ks = 0; ks < 2; ks++) {
                uint32_t ah[2][4], al[2][4];
#pragma unroll
                for (int mt = 0; mt < 2; mt++) {
                    uint32_t a0 = arow0 + (uint32_t)(mt * 16) * ASTRIDE + ks * 32;
                    ah[mt][0] = lds32(a0);
                    ah[mt][1] = lds32(a0 + 8 * ASTRIDE);
                    ah[mt][2] = lds32(a0 + 16);
                    ah[mt][3] = lds32(a0 + 8 * ASTRIDE + 16);
                    uint32_t a1 = a0 + A_LO_OFF;
                    al[mt][0] = lds32(a1);
                    al[mt][1] = lds32(a1 + 8 * ASTRIDE);
                    al[mt][2] = lds32(a1 + 16);
                    al[mt][3] = lds32(a1 + 8 * ASTRIDE + 16);
                }
                uint32_t bh[8][2], bl[8][2];
#pragma unroll
                for (int n = 0; n < 8; n++) {
                    uint32_t b0 = bbase + (uint32_t)(n * 8) * BSTRIDE + ks * 32;
                    bh[n][0] = lds32(b0);
                    bh[n][1] = lds32(b0 + 16);
                    bl[n][0] = lds32(b0 + B_LO_OFF);
                    bl[n][1] = lds32(b0 + B_LO_OFF + 16);
                }
#pragma unroll
                for (int n = 0; n < 8; n++)
#pragma unroll
                    for (int mt = 0; mt < 2; mt++) {
                        mma16816(acc[mt][n], ah[mt], bh[n]);
                        mma16816(acc[mt][n], ah[mt], bl[n]);
                        mma16816(acc[mt][n], al[mt], bh[n]);
                    }
            }
            __syncthreads();
        }
    }

    // ---- epilogue: direct register -> gmem ----
#pragma unroll
    for (int mt = 0; mt < 2; mt++) {
        int r0 = t0 + wm * 32 + mt * 16 + lr;
        int r1 = r0 + 8;
#pragma unroll
        for (int n = 0; n < 8; n++) {
            int o = o0 + wn * 64 + n * 8 + lc * 2;
            if (r0 < TOUT) {
                float2 v = make_float2(acc[mt][n][0], acc[mt][n][1]);
                *reinterpret_cast<float2*>(out + ((size_t)b * TOUT + r0) * CO + o) = v;
            }
            if (r1 < TOUT) {
                float2 v = make_float2(acc[mt][n][2], acc[mt][n][3]);
                *reinterpret_cast<float2*>(out + ((size_t)b * TOUT + r1) * CO + o) = v;
            }
        }
    }
}

// ---------------- launch ----------------
extern "C" void kernel_launch(void* const* d_in, const int* in_sizes, int n_in,
                              void* d_out, int out_size) {
    const float* x  = (const float*)d_in[0];
    const float* wr = (const float*)d_in[1];
    const float* wi = (const float*)d_in[2];
    const float* ph = (const float*)d_in[3];
    float* out = (float*)d_out;
    (void)in_sizes; (void)n_in; (void)out_size;

    cudaFuncSetAttribute(conv_mma_kernel,
                         cudaFuncAttributeMaxDynamicSharedMemorySize, SMEM_TOTAL);

    size_t nx = (size_t)NB * SPAD * CI;
    xprep_kernel<<<(unsigned)((nx + 255) / 256), 256>>>(x);
    int nw = KW * CO * CI;
    wprep_kernel<<<(nw + 255) / 256, 256>>>(wr, wi, ph);

    dim3 grid(SS / MT, NB, CO / NT);   // 16 x 32 x 2 = 1024 CTAs
    conv_mma_kernel<<<grid, 256, SMEM_TOTAL>>>(out);
}

// round 5
// speedup vs baseline: 2.7036x; 1.0317x over previous
#include <cuda_runtime.h>
#include <cuda_bf16.h>
#include <cstdint>

#define NB   32
#define SS   2048
#define SPAD 2064
#define CI   256
#define CO   256
#define KW   16
#define TOUT 2033

#define MT   128           // t rows per CTA
#define NT   128           // o cols per CTA
#define ICH  32            // i-channels per reduction chunk
#define NIC  (CI / ICH)    // 8
#define AROWS 143          // x rows per chunk (128 + 15)

#define ASTRIDE 80         // bytes/row in smem (32 bf16 = 64B + 16B pad)
#define BSTRIDE 80

#define A_LO_OFF (144 * ASTRIDE)            // 11520
#define A_BYTES  (2 * 144 * ASTRIDE)        // 23040
#define B_OFF    A_BYTES
#define B_LO_OFF (128 * BSTRIDE)            // within a stage
#define B_STAGE  (2 * 128 * BSTRIDE)        // 20480 (hi+lo)
#define SMEM_TOTAL (A_BYTES + 2 * B_STAGE)  // 64000

// ---------------- device scratch ----------------
__device__ __nv_bfloat16 g_xhi[(size_t)NB * SPAD * CI];
__device__ __nv_bfloat16 g_xlo[(size_t)NB * SPAD * CI];
__device__ __nv_bfloat16 g_whi[(size_t)KW * CO * CI];   // [k][o][i]
__device__ __nv_bfloat16 g_wlo[(size_t)KW * CO * CI];

// ---------------- helpers ----------------
__device__ __forceinline__ uint32_t s2u(const void* p) {
    uint32_t a;
    asm("{ .reg .u64 t; cvta.to.shared.u64 t, %1; cvt.u32.u64 %0, t; }"
        : "=r"(a) : "l"(p));
    return a;
}
__device__ __forceinline__ void cp16(uint32_t d, const void* s) {
    asm volatile("cp.async.cg.shared.global [%0], [%1], 16;" :: "r"(d), "l"(s));
}
__device__ __forceinline__ void cp_commit() {
    asm volatile("cp.async.commit_group;" ::: "memory");
}
__device__ __forceinline__ void cp_wait1() {
    asm volatile("cp.async.wait_group 1;" ::: "memory");
}
__device__ __forceinline__ void cp_wait0() {
    asm volatile("cp.async.wait_group 0;" ::: "memory");
}
__device__ __forceinline__ void ldm_x4(uint32_t* r, uint32_t a) {
    asm volatile("ldmatrix.sync.aligned.m8n8.x4.shared.b16 {%0,%1,%2,%3}, [%4];"
                 : "=r"(r[0]), "=r"(r[1]), "=r"(r[2]), "=r"(r[3]) : "r"(a));
}
__device__ __forceinline__ void mma16816(float* c, const uint32_t* a, const uint32_t* b) {
    asm volatile(
        "mma.sync.aligned.m16n8k16.row.col.f32.bf16.bf16.f32 "
        "{%0,%1,%2,%3}, {%4,%5,%6,%7}, {%8,%9}, {%0,%1,%2,%3};"
        : "+f"(c[0]), "+f"(c[1]), "+f"(c[2]), "+f"(c[3])
        : "r"(a[0]), "r"(a[1]), "r"(a[2]), "r"(a[3]), "r"(b[0]), "r"(b[1]));
}

// ---------------- prep kernels ----------------
__global__ void xprep_kernel(const float* __restrict__ x) {
    size_t idx4 = (size_t)blockIdx.x * 256 + threadIdx.x;
    if (idx4 >= (size_t)NB * SPAD * CI / 4) return;
    size_t idx = idx4 * 4;
    int i = idx & (CI - 1);
    size_t r = idx >> 8;
    int t = (int)(r % SPAD);
    int b = (int)(r / SPAD);
    float4 v = make_float4(0.f, 0.f, 0.f, 0.f);
    if (t < SS)
        v = *reinterpret_cast<const float4*>(x + ((size_t)b * SS + t) * CI + i);
    __nv_bfloat16 h0 = __float2bfloat16(v.x), h1 = __float2bfloat16(v.y);
    __nv_bfloat16 h2 = __float2bfloat16(v.z), h3 = __float2bfloat16(v.w);
    __nv_bfloat162* hi = reinterpret_cast<__nv_bfloat162*>(g_xhi + idx);
    __nv_bfloat162* lo = reinterpret_cast<__nv_bfloat162*>(g_xlo + idx);
    hi[0] = __nv_bfloat162(h0, h1);
    hi[1] = __nv_bfloat162(h2, h3);
    lo[0] = __nv_bfloat162(__float2bfloat16(v.x - __bfloat162float(h0)),
                           __float2bfloat16(v.y - __bfloat162float(h1)));
    lo[1] = __nv_bfloat162(__float2bfloat16(v.z - __bfloat162float(h2)),
                           __float2bfloat16(v.w - __bfloat162float(h3)));
}

__global__ void wprep_kernel(const float* __restrict__ wr,
                             const float* __restrict__ wi,
                             const float* __restrict__ ph) {
    int idx = blockIdx.x * 256 + threadIdx.x;
    if (idx >= KW * CO * CI) return;
    int i = idx & (CI - 1);
    int o = (idx >> 8) & (CO - 1);
    int k = idx >> 16;
    float s, c;
    sincosf(ph[k], &s, &c);
    int widx = (o * CI + i) * KW + k;            // w_real/w_imag are [o][i][k]
    float v = c * wr[widx] - s * wi[widx];
    __nv_bfloat16 h = __float2bfloat16(v);
    g_whi[idx] = h;
    g_wlo[idx] = __float2bfloat16(v - __bfloat162float(h));
}

// ---------------- main HMMA kernel ----------------
__global__ __launch_bounds__(256, 1)
void conv_mma_kernel(float* __restrict__ out) {
    extern __shared__ char smem[];
    const uint32_t sb = s2u(smem);
    const int tid = threadIdx.x;
    const int l = tid & 31, wid = tid >> 5;
    const int wm = wid & 3, wn = wid >> 2;      // warp grid 4(m) x 2(n)
    const int t0 = blockIdx.x * MT;
    const int b  = blockIdx.y;
    const int o0 = blockIdx.z * NT;

    const char* gxhi = (const char*)g_xhi;
    const char* gxlo = (const char*)g_xlo;
    const char* gwhi = (const char*)g_whi;
    const char* gwlo = (const char*)g_wlo;

    float acc[2][8][4];
#pragma unroll
    for (int mt = 0; mt < 2; mt++)
#pragma unroll
        for (int n = 0; n < 8; n++)
#pragma unroll
            for (int q = 0; q < 4; q++) acc[mt][n][q] = 0.f;

    // ldmatrix lane-address components
    const int lm = l & 15;                 // A: row within 16
    const int lg = l >> 4;                 // A: k-half (+16B)
    const int bo_row = (l & 7) + ((l >> 4) << 3);   // B: o-row within 16
    const int bhalf = (l >> 3) & 1;                 // B: k-half (+16B)

    for (int ic = 0; ic < NIC; ic++) {
        const size_t ioff = (size_t)ic * ICH * 2;   // byte offset into i dim

        // ---- A chunk (143 rows x 32 i, hi+lo), single-buffered ----
        for (int u = tid; u < AROWS * 4; u += 256) {
            int row = u >> 2, seg = u & 3;
            size_t g = ((size_t)(b * SPAD + t0 + row)) * (CI * 2) + ioff + seg * 16;
            uint32_t so = row * ASTRIDE + seg * 16;
            cp16(sb + so, gxhi + g);
            cp16(sb + A_LO_OFF + so, gxlo + g);
        }
        // ---- B[k=0] -> stage 0 ----
        {
            uint32_t bs = sb + B_OFF;
#pragma unroll
            for (int q = 0; q < 2; q++) {
                int u = q * 256 + tid;
                int o = u >> 2, seg = u & 3;
                size_t g = ((size_t)(o0 + o)) * (CI * 2) + ioff + seg * 16;
                cp16(bs + o * BSTRIDE + seg * 16, gwhi + g);
                cp16(bs + B_LO_OFF + o * BSTRIDE + seg * 16, gwlo + g);
            }
        }
        cp_commit();

        for (int k = 0; k < KW; k++) {
            const int s = k & 1;
            if (k + 1 < KW) {
                uint32_t bs = sb + B_OFF + (s ^ 1) * B_STAGE;
#pragma unroll
                for (int q = 0; q < 2; q++) {
                    int u = q * 256 + tid;
                    int o = u >> 2, seg = u & 3;
                    size_t g = ((size_t)((k + 1) * CO + o0 + o)) * (CI * 2) + ioff + seg * 16;
                    cp16(bs + o * BSTRIDE + seg * 16, gwhi + g);
                    cp16(bs + B_LO_OFF + o * BSTRIDE + seg * 16, gwlo + g);
                }
                cp_commit();
                cp_wait1();
            } else {
                cp_wait0();
            }
            __syncthreads();

            const uint32_t a_base = sb + (uint32_t)(k + wm * 32 + lm) * ASTRIDE + lg * 16;
            const uint32_t b_base = sb + B_OFF + s * B_STAGE
                                  + (uint32_t)(wn * 64 + bo_row) * BSTRIDE + bhalf * 16;
#pragma unroll
            for (int ks = 0; ks < 2; ks++) {
                uint32_t ah[2][4], al[2][4];
#pragma unroll
                for (int mt = 0; mt < 2; mt++) {
                    uint32_t a0 = a_base + (uint32_t)(mt * 16) * ASTRIDE + ks * 32;
                    ldm_x4(ah[mt], a0);
                    ldm_x4(al[mt], a0 + A_LO_OFF);
                }
                uint32_t bh[4][4], bl[4][4];     // each x4 covers 2 n8-tiles
#pragma unroll
                for (int p = 0; p < 4; p++) {
                    uint32_t b0 = b_base + (uint32_t)(p * 16) * BSTRIDE + ks * 32;
                    ldm_x4(bh[p], b0);
                    ldm_x4(bl[p], b0 + B_LO_OFF);
                }
#pragma unroll
                for (int n = 0; n < 8; n++) {
                    const uint32_t* bhp = &bh[n >> 1][(n & 1) * 2];
                    const uint32_t* blp = &bl[n >> 1][(n & 1) * 2];
#pragma unroll
                    for (int mt = 0; mt < 2; mt++) {
                        mma16816(acc[mt][n], ah[mt], bhp);
                        mma16816(acc[mt][n], ah[mt], blp);
                        mma16816(acc[mt][n], al[mt], bhp);
                    }
                }
            }
            __syncthreads();
        }
    }

    // ---- epilogue: direct register -> gmem ----
    const int lr = l >> 2, lc = l & 3;
#pragma unroll
    for (int mt = 0; mt < 2; mt++) {
        int r0 = t0 + wm * 32 + mt * 16 + lr;
        int r1 = r0 + 8;
#pragma unroll
        for (int n = 0; n < 8; n++) {
            int o = o0 + wn * 64 + n * 8 + lc * 2;
            if (r0 < TOUT) {
                float2 v = make_float2(acc[mt][n][0], acc[mt][n][1]);
                *reinterpret_cast<float2*>(out + ((size_t)b * TOUT + r0) * CO + o) = v;
            }
            if (r1 < TOUT) {
                float2 v = make_float2(acc[mt][n][2], acc[mt][n][3]);
                *reinterpret_cast<float2*>(out + ((size_t)b * TOUT + r1) * CO + o) = v;
            }
        }
    }
}

// ---------------- launch ----------------
extern "C" void kernel_launch(void* const* d_in, const int* in_sizes, int n_in,
                              void* d_out, int out_size) {
    const float* x  = (const float*)d_in[0];
    const float* wr = (const float*)d_in[1];
    const float* wi = (const float*)d_in[2];
    const float* ph = (const float*)d_in[3];
    float* out = (float*)d_out;
    (void)in_sizes; (void)n_in; (void)out_size;

    cudaFuncSetAttribute(conv_mma_kernel,
                         cudaFuncAttributeMaxDynamicSharedMemorySize, SMEM_TOTAL);

    size_t nx4 = (size_t)NB * SPAD * CI / 4;
    xprep_kernel<<<(unsigned)((nx4 + 255) / 256), 256>>>(x);
    int nw = KW * CO * CI;
    wprep_kernel<<<(nw + 255) / 256, 256>>>(wr, wi, ph);

    dim3 grid(SS / MT, NB, CO / NT);   // 16 x 32 x 2 = 1024 CTAs
    conv_mma_kernel<<<grid, 256, SMEM_TOTAL>>>(out);
}